// round 1
// baseline (speedup 1.0000x reference)
#include <cuda_runtime.h>
#include <math.h>

#define B    8
#define KB   16
#define SEQ  512
#define HID  768

#define BM   128
#define BN   128
#define BKC  8
#define STILES (SEQ / BM)   // 4

// Scratch (no cudaMalloc allowed)
__device__ float g_qn[B * SEQ * HID];
__device__ float g_kn[KB * SEQ * HID];
__device__ float g_part[STILES * B * KB];

// ---------------------------------------------------------------------------
// L2-normalize rows of Q and K. One warp per row of 768 floats.
// ---------------------------------------------------------------------------
__global__ void normalize_kernel(const float* __restrict__ q,
                                 const float* __restrict__ k) {
    int warp_id = (blockIdx.x * blockDim.x + threadIdx.x) >> 5;
    int lane    = threadIdx.x & 31;
    const int total = (B + KB) * SEQ;
    if (warp_id >= total) return;

    const float* src;
    float*       dst;
    if (warp_id < B * SEQ) {
        src = q + (size_t)warp_id * HID;
        dst = g_qn + (size_t)warp_id * HID;
    } else {
        int r = warp_id - B * SEQ;
        src = k + (size_t)r * HID;
        dst = g_kn + (size_t)r * HID;
    }

    const float4* s4 = (const float4*)src;
    float4 v[6];
    float ss = 0.f;
#pragma unroll
    for (int i = 0; i < 6; i++) {
        v[i] = s4[lane + 32 * i];
        ss += v[i].x * v[i].x + v[i].y * v[i].y + v[i].z * v[i].z + v[i].w * v[i].w;
    }
#pragma unroll
    for (int o = 16; o > 0; o >>= 1) ss += __shfl_xor_sync(0xffffffffu, ss, o);

    float inv = 1.0f / fmaxf(sqrtf(ss), 1e-12f);
    float4* d4 = (float4*)dst;
#pragma unroll
    for (int i = 0; i < 6; i++) {
        float4 w = v[i];
        w.x *= inv; w.y *= inv; w.z *= inv; w.w *= inv;
        d4[lane + 32 * i] = w;
    }
}

// ---------------------------------------------------------------------------
// Fused cos-GEMM + distance weighting + masked online softmax + score reduce.
// One CTA = one (i, j, s-tile). 256 threads, 8x8 micro-tile -> 128x128 C tile.
// ---------------------------------------------------------------------------
__global__ __launch_bounds__(256) void late_kernel(
    const float* __restrict__ alpha_raw,
    const int*   __restrict__ q_mask,
    const int*   __restrict__ k_mask) {

    __shared__ float As[BKC][BM];
    __shared__ float Bs[BKC][BN];
    __shared__ float red[256];

    const int i  = blockIdx.z;
    const int j  = blockIdx.y;
    const int s0 = blockIdx.x * BM;

    const int tid = threadIdx.x;
    const int ty  = tid >> 4;    // 0..15 (row group: rows ty*8 .. ty*8+7)
    const int tx  = tid & 15;    // 0..15 (col group: cols tx*8 .. tx*8+7)

    const float ar    = *alpha_raw;
    const float alpha = ar > 0.f ? ar : 0.01f * ar;   // leaky_relu

    const float* Qb = g_qn + ((size_t)i * SEQ + s0) * HID;
    const float* Kb = g_kn + ((size_t)j * SEQ) * HID;

    // Per-row constants: exp(-alpha*s), exp(+alpha*s), q_mask
    float ern[8], erp[8], qmf[8];
#pragma unroll
    for (int r = 0; r < 8; r++) {
        int s = s0 + ty * 8 + r;
        float as = alpha * (float)s;
        ern[r] = __expf(-as);
        erp[r] = __expf(as);
        qmf[r] = (float)q_mask[i * SEQ + s];
    }

    // Online softmax state (replicated across the 16 tx lanes of a row group)
    float mrow[8], den[8], num[8];
#pragma unroll
    for (int r = 0; r < 8; r++) { mrow[r] = -INFINITY; den[r] = 0.f; num[r] = 0.f; }

    const int grow = tid >> 1;          // 0..127 : row loaded by this thread
    const int gpart = (tid & 1) * 4;    // 0 or 4 : float4 slot within BK=8

    for (int t0 = 0; t0 < SEQ; t0 += BN) {
        float acc[8][8];
#pragma unroll
        for (int r = 0; r < 8; r++)
#pragma unroll
            for (int c = 0; c < 8; c++) acc[r][c] = 0.f;

        const float* qsrc = Qb + (size_t)grow * HID + gpart;
        const float* ksrc = Kb + ((size_t)(t0 + grow)) * HID + gpart;

        float4 qv = *(const float4*)(qsrc);
        float4 kv = *(const float4*)(ksrc);

        for (int kk = 0; kk < HID; kk += BKC) {
            __syncthreads();
            As[gpart + 0][grow] = qv.x; As[gpart + 1][grow] = qv.y;
            As[gpart + 2][grow] = qv.z; As[gpart + 3][grow] = qv.w;
            Bs[gpart + 0][grow] = kv.x; Bs[gpart + 1][grow] = kv.y;
            Bs[gpart + 2][grow] = kv.z; Bs[gpart + 3][grow] = kv.w;
            __syncthreads();

            if (kk + BKC < HID) {
                qv = *(const float4*)(qsrc + kk + BKC);
                kv = *(const float4*)(ksrc + kk + BKC);
            }

#pragma unroll
            for (int k = 0; k < BKC; k++) {
                float4 a0 = *(const float4*)&As[k][ty * 8];
                float4 a1 = *(const float4*)&As[k][ty * 8 + 4];
                float4 b0 = *(const float4*)&Bs[k][tx * 8];
                float4 b1 = *(const float4*)&Bs[k][tx * 8 + 4];
                float a[8] = {a0.x, a0.y, a0.z, a0.w, a1.x, a1.y, a1.z, a1.w};
                float b[8] = {b0.x, b0.y, b0.z, b0.w, b1.x, b1.y, b1.z, b1.w};
#pragma unroll
                for (int r = 0; r < 8; r++)
#pragma unroll
                    for (int c = 0; c < 8; c++)
                        acc[r][c] = fmaf(a[r], b[c], acc[r][c]);
            }
        }

        // ---- epilogue: distance weight + masked online softmax ----
        float ecn[8], ecp[8], kmf[8];
#pragma unroll
        for (int c = 0; c < 8; c++) {
            int t = t0 + tx * 8 + c;
            float at = alpha * (float)t;
            ecn[c] = __expf(-at);
            ecp[c] = __expf(at);
            kmf[c] = (float)k_mask[j * SEQ + t];
        }

        // pass 1: masked row max of w = cos * exp(-alpha*|s-t|)
        float rmax[8];
#pragma unroll
        for (int r = 0; r < 8; r++) {
            int s = s0 + ty * 8 + r;
            float mx = -INFINITY;
#pragma unroll
            for (int c = 0; c < 8; c++) {
                int t = t0 + tx * 8 + c;
                float dw = (s >= t) ? ern[r] * ecp[c] : erp[r] * ecn[c];
                float w  = acc[r][c] * dw;
                mx = (kmf[c] != 0.f) ? fmaxf(mx, w) : mx;
            }
            rmax[r] = mx;
        }
#pragma unroll
        for (int r = 0; r < 8; r++)
#pragma unroll
            for (int o = 1; o < 16; o <<= 1)
                rmax[r] = fmaxf(rmax[r], __shfl_xor_sync(0xffffffffu, rmax[r], o));

        // pass 2: branch-free rescale + accumulate (keeps shuffles convergent)
#pragma unroll
        for (int r = 0; r < 8; r++) {
            int s = s0 + ty * 8 + r;
            float mn  = fmaxf(mrow[r], rmax[r]);
            float any = (mn != -INFINITY) ? 1.f : 0.f;
            float mnx = (mn != -INFINITY) ? mn : 0.f;
            float scale = (mrow[r] != -INFINITY) ? __expf(mrow[r] - mnx) : 0.f;

            float dl = 0.f, nl = 0.f;
#pragma unroll
            for (int c = 0; c < 8; c++) {
                int t = t0 + tx * 8 + c;
                float dw = (s >= t) ? ern[r] * ecp[c] : erp[r] * ecn[c];
                float w  = acc[r][c] * dw;
                float e  = __expf(w - mnx) * kmf[c] * any;
                dl += e;
                nl += e * acc[r][c];
            }
#pragma unroll
            for (int o = 1; o < 16; o <<= 1) {
                dl += __shfl_xor_sync(0xffffffffu, dl, o);
                nl += __shfl_xor_sync(0xffffffffu, nl, o);
            }
            den[r]  = den[r] * scale + dl;
            num[r]  = num[r] * scale + nl;
            mrow[r] = (mn != -INFINITY) ? mn : mrow[r];
        }
    }

    // ---- final: score_s = num/den (0 if empty), * q_mask, sum over tile ----
    float local = 0.f;
    if (tx == 0) {
#pragma unroll
        for (int r = 0; r < 8; r++) {
            float sc = (den[r] > 0.f) ? num[r] / den[r] : 0.f;
            local += sc * qmf[r];
        }
    }
    red[tid] = local;
    __syncthreads();
    for (int step = 128; step > 0; step >>= 1) {
        if (tid < step) red[tid] += red[tid + step];
        __syncthreads();
    }
    if (tid == 0)
        g_part[blockIdx.x * (B * KB) + i * KB + j] = red[0];
}

// ---------------------------------------------------------------------------
// Sum s-tile partials -> out[B,KB]. Deterministic (no atomics).
// ---------------------------------------------------------------------------
__global__ void reduce_out_kernel(float* __restrict__ out) {
    int idx = threadIdx.x;
    if (idx < B * KB) {
        float s = 0.f;
#pragma unroll
        for (int p = 0; p < STILES; p++) s += g_part[p * (B * KB) + idx];
        out[idx] = s;
    }
}

// ---------------------------------------------------------------------------
extern "C" void kernel_launch(void* const* d_in, const int* in_sizes, int n_in,
                              void* d_out, int out_size) {
    const float* q     = (const float*)d_in[0];
    const float* k     = (const float*)d_in[1];
    const float* alpha = (const float*)d_in[2];
    const int*   qm    = (const int*)d_in[3];
    const int*   km    = (const int*)d_in[4];
    float*       out   = (float*)d_out;

    // 12288 rows, one warp each, 8 warps/block
    normalize_kernel<<<((B + KB) * SEQ) / 8, 256>>>(q, k);

    dim3 grid(STILES, KB, B);
    late_kernel<<<grid, 256>>>(alpha, qm, km);

    reduce_out_kernel<<<1, 128>>>(out);
}

// round 2
// speedup vs baseline: 1.0011x; 1.0011x over previous
#include <cuda_runtime.h>
#include <math.h>

#define B    8
#define KB   16
#define SEQ  512
#define HID  768

#define BM   128
#define BN   128
#define BKC  8
#define STILES (SEQ / BM)   // 4

// Scratch (no cudaMalloc allowed)
__device__ float g_qn[B * SEQ * HID];
__device__ float g_kn[KB * SEQ * HID];
__device__ float g_part[STILES * B * KB];

// ---------------------------------------------------------------------------
// L2-normalize rows of Q and K. One warp per row of 768 floats.
// ---------------------------------------------------------------------------
__global__ void normalize_kernel(const float* __restrict__ q,
                                 const float* __restrict__ k) {
    int warp_id = (blockIdx.x * blockDim.x + threadIdx.x) >> 5;
    int lane    = threadIdx.x & 31;
    const int total = (B + KB) * SEQ;
    if (warp_id >= total) return;

    const float* src;
    float*       dst;
    if (warp_id < B * SEQ) {
        src = q + (size_t)warp_id * HID;
        dst = g_qn + (size_t)warp_id * HID;
    } else {
        int r = warp_id - B * SEQ;
        src = k + (size_t)r * HID;
        dst = g_kn + (size_t)r * HID;
    }

    const float4* s4 = (const float4*)src;
    float4 v[6];
    float ss = 0.f;
#pragma unroll
    for (int i = 0; i < 6; i++) {
        v[i] = s4[lane + 32 * i];
        ss += v[i].x * v[i].x + v[i].y * v[i].y + v[i].z * v[i].z + v[i].w * v[i].w;
    }
#pragma unroll
    for (int o = 16; o > 0; o >>= 1) ss += __shfl_xor_sync(0xffffffffu, ss, o);

    float inv = 1.0f / fmaxf(sqrtf(ss), 1e-12f);
    float4* d4 = (float4*)dst;
#pragma unroll
    for (int i = 0; i < 6; i++) {
        float4 w = v[i];
        w.x *= inv; w.y *= inv; w.z *= inv; w.w *= inv;
        d4[lane + 32 * i] = w;
    }
}

// ---------------------------------------------------------------------------
// Fused cos-GEMM + distance weighting + masked online softmax + score reduce.
// One CTA = one (i, j, s-tile). 256 threads, 8x8 micro-tile -> 128x128 C tile.
// ---------------------------------------------------------------------------
__global__ __launch_bounds__(256) void late_kernel(
    const float* __restrict__ alpha_raw,
    const int*   __restrict__ q_mask,
    const int*   __restrict__ k_mask) {

    __shared__ float As[BKC][BM];
    __shared__ float Bs[BKC][BN];
    __shared__ float red[256];

    const int i  = blockIdx.z;
    const int j  = blockIdx.y;
    const int s0 = blockIdx.x * BM;

    const int tid = threadIdx.x;
    const int ty  = tid >> 4;    // 0..15 (row group: rows ty*8 .. ty*8+7)
    const int tx  = tid & 15;    // 0..15 (col group: cols tx*8 .. tx*8+7)

    const float ar    = *alpha_raw;
    const float alpha = ar > 0.f ? ar : 0.01f * ar;   // leaky_relu

    const float* Qb = g_qn + ((size_t)i * SEQ + s0) * HID;
    const float* Kb = g_kn + ((size_t)j * SEQ) * HID;

    // Per-row constants: exp(-alpha*s), exp(+alpha*s), q_mask
    float ern[8], erp[8], qmf[8];
#pragma unroll
    for (int r = 0; r < 8; r++) {
        int s = s0 + ty * 8 + r;
        float as = alpha * (float)s;
        ern[r] = __expf(-as);
        erp[r] = __expf(as);
        qmf[r] = (float)q_mask[i * SEQ + s];
    }

    // Online softmax state (replicated across the 16 tx lanes of a row group)
    float mrow[8], den[8], num[8];
#pragma unroll
    for (int r = 0; r < 8; r++) { mrow[r] = -INFINITY; den[r] = 0.f; num[r] = 0.f; }

    const int grow = tid >> 1;          // 0..127 : row loaded by this thread
    const int gpart = (tid & 1) * 4;    // 0 or 4 : float4 slot within BK=8

    for (int t0 = 0; t0 < SEQ; t0 += BN) {
        float acc[8][8];
#pragma unroll
        for (int r = 0; r < 8; r++)
#pragma unroll
            for (int c = 0; c < 8; c++) acc[r][c] = 0.f;

        const float* qsrc = Qb + (size_t)grow * HID + gpart;
        const float* ksrc = Kb + ((size_t)(t0 + grow)) * HID + gpart;

        float4 qv = *(const float4*)(qsrc);
        float4 kv = *(const float4*)(ksrc);

        for (int kk = 0; kk < HID; kk += BKC) {
            __syncthreads();
            As[gpart + 0][grow] = qv.x; As[gpart + 1][grow] = qv.y;
            As[gpart + 2][grow] = qv.z; As[gpart + 3][grow] = qv.w;
            Bs[gpart + 0][grow] = kv.x; Bs[gpart + 1][grow] = kv.y;
            Bs[gpart + 2][grow] = kv.z; Bs[gpart + 3][grow] = kv.w;
            __syncthreads();

            if (kk + BKC < HID) {
                qv = *(const float4*)(qsrc + kk + BKC);
                kv = *(const float4*)(ksrc + kk + BKC);
            }

#pragma unroll
            for (int k = 0; k < BKC; k++) {
                float4 a0 = *(const float4*)&As[k][ty * 8];
                float4 a1 = *(const float4*)&As[k][ty * 8 + 4];
                float4 b0 = *(const float4*)&Bs[k][tx * 8];
                float4 b1 = *(const float4*)&Bs[k][tx * 8 + 4];
                float a[8] = {a0.x, a0.y, a0.z, a0.w, a1.x, a1.y, a1.z, a1.w};
                float b[8] = {b0.x, b0.y, b0.z, b0.w, b1.x, b1.y, b1.z, b1.w};
#pragma unroll
                for (int r = 0; r < 8; r++)
#pragma unroll
                    for (int c = 0; c < 8; c++)
                        acc[r][c] = fmaf(a[r], b[c], acc[r][c]);
            }
        }

        // ---- epilogue: distance weight + masked online softmax ----
        float ecn[8], ecp[8], kmf[8];
#pragma unroll
        for (int c = 0; c < 8; c++) {
            int t = t0 + tx * 8 + c;
            float at = alpha * (float)t;
            ecn[c] = __expf(-at);
            ecp[c] = __expf(at);
            kmf[c] = (float)k_mask[j * SEQ + t];
        }

        // pass 1: masked row max of w = cos * exp(-alpha*|s-t|)
        float rmax[8];
#pragma unroll
        for (int r = 0; r < 8; r++) {
            int s = s0 + ty * 8 + r;
            float mx = -INFINITY;
#pragma unroll
            for (int c = 0; c < 8; c++) {
                int t = t0 + tx * 8 + c;
                float dw = (s >= t) ? ern[r] * ecp[c] : erp[r] * ecn[c];
                float w  = acc[r][c] * dw;
                mx = (kmf[c] != 0.f) ? fmaxf(mx, w) : mx;
            }
            rmax[r] = mx;
        }
#pragma unroll
        for (int r = 0; r < 8; r++)
#pragma unroll
            for (int o = 1; o < 16; o <<= 1)
                rmax[r] = fmaxf(rmax[r], __shfl_xor_sync(0xffffffffu, rmax[r], o));

        // pass 2: branch-free rescale + accumulate (keeps shuffles convergent)
#pragma unroll
        for (int r = 0; r < 8; r++) {
            int s = s0 + ty * 8 + r;
            float mn  = fmaxf(mrow[r], rmax[r]);
            float any = (mn != -INFINITY) ? 1.f : 0.f;
            float mnx = (mn != -INFINITY) ? mn : 0.f;
            float scale = (mrow[r] != -INFINITY) ? __expf(mrow[r] - mnx) : 0.f;

            float dl = 0.f, nl = 0.f;
#pragma unroll
            for (int c = 0; c < 8; c++) {
                int t = t0 + tx * 8 + c;
                float dw = (s >= t) ? ern[r] * ecp[c] : erp[r] * ecn[c];
                float w  = acc[r][c] * dw;
                float e  = __expf(w - mnx) * kmf[c] * any;
                dl += e;
                nl += e * acc[r][c];
            }
#pragma unroll
            for (int o = 1; o < 16; o <<= 1) {
                dl += __shfl_xor_sync(0xffffffffu, dl, o);
                nl += __shfl_xor_sync(0xffffffffu, nl, o);
            }
            den[r]  = den[r] * scale + dl;
            num[r]  = num[r] * scale + nl;
            mrow[r] = (mn != -INFINITY) ? mn : mrow[r];
        }
    }

    // ---- final: score_s = num/den (0 if empty), * q_mask, sum over tile ----
    float local = 0.f;
    if (tx == 0) {
#pragma unroll
        for (int r = 0; r < 8; r++) {
            float sc = (den[r] > 0.f) ? num[r] / den[r] : 0.f;
            local += sc * qmf[r];
        }
    }
    red[tid] = local;
    __syncthreads();
    for (int step = 128; step > 0; step >>= 1) {
        if (tid < step) red[tid] += red[tid + step];
        __syncthreads();
    }
    if (tid == 0)
        g_part[blockIdx.x * (B * KB) + i * KB + j] = red[0];
}

// ---------------------------------------------------------------------------
// Sum s-tile partials -> out[B,KB]. Deterministic (no atomics).
// ---------------------------------------------------------------------------
__global__ void reduce_out_kernel(float* __restrict__ out) {
    int idx = threadIdx.x;
    if (idx < B * KB) {
        float s = 0.f;
#pragma unroll
        for (int p = 0; p < STILES; p++) s += g_part[p * (B * KB) + idx];
        out[idx] = s;
    }
}

// ---------------------------------------------------------------------------
extern "C" void kernel_launch(void* const* d_in, const int* in_sizes, int n_in,
                              void* d_out, int out_size) {
    const float* q     = (const float*)d_in[0];
    const float* k     = (const float*)d_in[1];
    const float* alpha = (const float*)d_in[2];
    const int*   qm    = (const int*)d_in[3];
    const int*   km    = (const int*)d_in[4];
    float*       out   = (float*)d_out;

    // 12288 rows, one warp each, 8 warps/block
    normalize_kernel<<<((B + KB) * SEQ) / 8, 256>>>(q, k);

    dim3 grid(STILES, KB, B);
    late_kernel<<<grid, 256>>>(alpha, qm, km);

    reduce_out_kernel<<<1, 128>>>(out);
}

// round 4
// speedup vs baseline: 5.4024x; 5.3967x over previous
#include <cuda_runtime.h>
#include <cuda_fp16.h>
#include <math.h>
#include <stdint.h>

#define B_    8
#define KB_   16
#define SEQ_  512
#define HID_  768

#define BM 128
#define BN 128
#define BK 32
#define NKT (HID_ / BK)        // 24 k-iterations
#define ROWH 40                // padded halfs per smem row (80 bytes)
#define TILE_HALFS (128 * ROWH)
#define STAGE_BYTES (2 * TILE_HALFS * 2)   // A tile + B tile, bytes (20480)
#define KM_OFF  (3 * STAGE_BYTES)          // 61440
#define SDN_OFF (KM_OFF + 512)             // 61952
#define SMEM_DYN (SDN_OFF + 2048)          // 64000

__device__ __half g_qh[B_ * SEQ_ * HID_];
__device__ __half g_kh[KB_ * SEQ_ * HID_];
__device__ float2 g_dn[4 * B_ * KB_ * SEQ_];   // [t_tile][i][j][s]

// ---------------- PTX helpers (baseline sm_80-level, no 'a' features) -------
__device__ __forceinline__ uint32_t smem_u32(const void* p) {
    uint32_t a;
    asm("{ .reg .u64 t; cvta.to.shared.u64 t, %1; cvt.u32.u64 %0, t; }" : "=r"(a) : "l"(p));
    return a;
}
#define CP_ASYNC16(dst, src) \
    asm volatile("cp.async.cg.shared.global [%0], [%1], 16;" :: "r"(dst), "l"(src))
#define CP_COMMIT() asm volatile("cp.async.commit_group;" ::: "memory")
#define CP_WAIT(n)  asm volatile("cp.async.wait_group %0;" :: "n"(n) : "memory")

#define LDMATRIX_X4(r0, r1, r2, r3, addr) \
    asm volatile("ldmatrix.sync.aligned.m8n8.x4.shared.b16 {%0,%1,%2,%3}, [%4];" \
        : "=r"(r0), "=r"(r1), "=r"(r2), "=r"(r3) : "r"(addr))
#define LDMATRIX_X2(r0, r1, addr) \
    asm volatile("ldmatrix.sync.aligned.m8n8.x2.shared.b16 {%0,%1}, [%2];" \
        : "=r"(r0), "=r"(r1) : "r"(addr))

#define MMA16816(d, a, b) \
    asm volatile("mma.sync.aligned.m16n8k16.row.col.f32.f16.f16.f32 " \
        "{%0,%1,%2,%3}, {%4,%5,%6,%7}, {%8,%9}, {%0,%1,%2,%3};" \
        : "+f"((d)[0]), "+f"((d)[1]), "+f"((d)[2]), "+f"((d)[3]) \
        : "r"((a)[0]), "r"((a)[1]), "r"((a)[2]), "r"((a)[3]), "r"((b)[0]), "r"((b)[1]))

// ---------------------------------------------------------------------------
// L2-normalize rows, convert to fp16. One warp per row of 768 floats.
// ---------------------------------------------------------------------------
__global__ void normalize_kernel(const float* __restrict__ q,
                                 const float* __restrict__ k) {
    int warp_id = (blockIdx.x * blockDim.x + threadIdx.x) >> 5;
    int lane = threadIdx.x & 31;
    if (warp_id >= (B_ + KB_) * SEQ_) return;

    const float* src;
    __half* dst;
    if (warp_id < B_ * SEQ_) {
        src = q + (size_t)warp_id * HID_;
        dst = g_qh + (size_t)warp_id * HID_;
    } else {
        int r = warp_id - B_ * SEQ_;
        src = k + (size_t)r * HID_;
        dst = g_kh + (size_t)r * HID_;
    }

    const float4* s4 = (const float4*)src;
    float4 v[6];
    float ss = 0.f;
#pragma unroll
    for (int g = 0; g < 6; g++) {
        v[g] = s4[lane + 32 * g];
        ss += v[g].x*v[g].x + v[g].y*v[g].y + v[g].z*v[g].z + v[g].w*v[g].w;
    }
#pragma unroll
    for (int o = 16; o > 0; o >>= 1) ss += __shfl_xor_sync(0xffffffffu, ss, o);
    float inv = 1.0f / fmaxf(sqrtf(ss), 1e-12f);

#pragma unroll
    for (int g = 0; g < 6; g++) {
        __half2 h0 = __floats2half2_rn(v[g].x * inv, v[g].y * inv);
        __half2 h1 = __floats2half2_rn(v[g].z * inv, v[g].w * inv);
        uint2 pk;
        pk.x = *(uint32_t*)&h0;
        pk.y = *(uint32_t*)&h1;
        *(uint2*)(dst + (lane + 32 * g) * 4) = pk;
    }
}

// ---------------------------------------------------------------------------
// HMMA GEMM + fused distance-weight/softmax partial epilogue.
// CTA = (s_tile, t_tile, j, i): 128x128 tile of cos, K=768 fp16.
// 8 warps: 4(m) x 2(n); warp tile 32x64 = 2(m16) x 8(n8) mma grid.
// ---------------------------------------------------------------------------
__global__ __launch_bounds__(256, 1) void late_kernel(
    const float* __restrict__ alpha_raw,
    const int*   __restrict__ k_mask) {

    extern __shared__ __align__(16) char smem[];
    const uint32_t sb = smem_u32(smem);
    float*  km  = (float*)(smem + KM_OFF);
    float2* sdn = (float2*)(smem + SDN_OFF);   // [2][128]

    const int tid = threadIdx.x, wid = tid >> 5, lane = tid & 31;
    const int st = blockIdx.x & 3, tt = blockIdx.x >> 2;
    const int j = blockIdx.y, i = blockIdx.z;
    const int wm = wid & 3, wn = wid >> 2;

    if (tid < 128) km[tid] = (float)k_mask[j * SEQ_ + tt * 128 + tid];

    // cp.async source rows for this thread
    const int ldr = tid >> 1;              // row 0..127
    const int ldc = (tid & 1) * 2;         // 16B-chunk pair: {ldc, ldc+1} of 4
    const __half* Arow = g_qh + ((size_t)(i * SEQ_ + st * 128 + ldr)) * HID_;
    const __half* Brow = g_kh + ((size_t)(j * SEQ_ + tt * 128 + ldr)) * HID_;
    const uint32_t dstA = sb + ldr * 80 + ldc * 16;
    const uint32_t dstB = dstA + TILE_HALFS * 2;

    // prologue: stages 0,1
#pragma unroll
    for (int p = 0; p < 2; p++) {
        uint32_t o = p * STAGE_BYTES;
        const __half* a = Arow + p * BK + ldc * 8;
        const __half* b = Brow + p * BK + ldc * 8;
        CP_ASYNC16(dstA + o,      a);
        CP_ASYNC16(dstA + o + 16, a + 8);
        CP_ASYNC16(dstB + o,      b);
        CP_ASYNC16(dstB + o + 16, b + 8);
        CP_COMMIT();
    }

    float acc[2][8][4];
#pragma unroll
    for (int mi = 0; mi < 2; mi++)
#pragma unroll
        for (int ni = 0; ni < 8; ni++)
#pragma unroll
            for (int e = 0; e < 4; e++) acc[mi][ni][e] = 0.f;

    // ldmatrix addresses (fixed per thread, advance by stage)
    const uint32_t aAddrBase = sb + (wm * 32 + (lane & 15)) * 80 + ((lane >> 4) * 8) * 2;
    const uint32_t bAddrBase = sb + TILE_HALFS * 2 + (wn * 64 + (lane & 7)) * 80 + (((lane >> 3) & 1) * 8) * 2;

    for (int kt = 0; kt < NKT; kt++) {
        if (kt < NKT - 1) { CP_WAIT(1); } else { CP_WAIT(0); }
        __syncthreads();

        // prefetch stage kt+2
        if (kt + 2 < NKT) {
            uint32_t o = ((kt + 2) % 3) * STAGE_BYTES;
            const __half* a = Arow + (kt + 2) * BK + ldc * 8;
            const __half* b = Brow + (kt + 2) * BK + ldc * 8;
            CP_ASYNC16(dstA + o,      a);
            CP_ASYNC16(dstA + o + 16, a + 8);
            CP_ASYNC16(dstB + o,      b);
            CP_ASYNC16(dstB + o + 16, b + 8);
            CP_COMMIT();
        }

        const uint32_t so = (kt % 3) * STAGE_BYTES;
#pragma unroll
        for (int k16 = 0; k16 < 2; k16++) {
            uint32_t af0[4], af1[4];
            LDMATRIX_X4(af0[0], af0[1], af0[2], af0[3], aAddrBase + so + k16 * 32);
            LDMATRIX_X4(af1[0], af1[1], af1[2], af1[3], aAddrBase + so + 16 * 80 + k16 * 32);
            uint32_t bf[8][2];
#pragma unroll
            for (int ni = 0; ni < 8; ni++)
                LDMATRIX_X2(bf[ni][0], bf[ni][1], bAddrBase + so + ni * 8 * 80 + k16 * 32);
#pragma unroll
            for (int ni = 0; ni < 8; ni++) {
                MMA16816(acc[0][ni], af0, bf[ni]);
                MMA16816(acc[1][ni], af1, bf[ni]);
            }
        }
    }
    __syncthreads();

    // ---- epilogue: dw + exp + masked den/num partials ----
    const float ar = *alpha_raw;
    const float alpha = ar > 0.f ? ar : 0.01f * ar;

    float den[4] = {0.f, 0.f, 0.f, 0.f};
    float num[4] = {0.f, 0.f, 0.f, 0.f};
#pragma unroll
    for (int mi = 0; mi < 2; mi++) {
#pragma unroll
        for (int h = 0; h < 2; h++) {
            const int rloc = wm * 32 + mi * 16 + (lane >> 2) + h * 8;
            const float sv = (float)(st * 128 + rloc);
#pragma unroll
            for (int ni = 0; ni < 8; ni++) {
#pragma unroll
                for (int e = 0; e < 2; e++) {
                    const int cloc = wn * 64 + ni * 8 + (lane & 3) * 2 + e;
                    const float tv = (float)(tt * 128 + cloc);
                    const float cosv = acc[mi][ni][h * 2 + e];
                    const float dw = __expf(-alpha * fabsf(sv - tv));
                    const float ev = __expf(cosv * dw) * km[cloc];
                    den[mi * 2 + h] += ev;
                    num[mi * 2 + h] = fmaf(ev, cosv, num[mi * 2 + h]);
                }
            }
        }
    }
    // quad reduce (lanes sharing a row)
#pragma unroll
    for (int idx = 0; idx < 4; idx++) {
#pragma unroll
        for (int o = 1; o < 4; o <<= 1) {
            den[idx] += __shfl_xor_sync(0xffffffffu, den[idx], o);
            num[idx] += __shfl_xor_sync(0xffffffffu, num[idx], o);
        }
    }
    if ((lane & 3) == 0) {
#pragma unroll
        for (int mi = 0; mi < 2; mi++)
#pragma unroll
            for (int h = 0; h < 2; h++) {
                int rloc = wm * 32 + mi * 16 + (lane >> 2) + h * 8;
                sdn[wn * 128 + rloc] = make_float2(den[mi * 2 + h], num[mi * 2 + h]);
            }
    }
    __syncthreads();
    if (tid < 128) {
        float2 a = sdn[tid], b = sdn[128 + tid];
        g_dn[((size_t)tt * (B_ * KB_) + i * KB_ + j) * SEQ_ + st * 128 + tid] =
            make_float2(a.x + b.x, a.y + b.y);
    }
}

// ---------------------------------------------------------------------------
__global__ void reduce_kernel(const int* __restrict__ q_mask, float* __restrict__ out) {
    __shared__ float red[256];
    const int ij = blockIdx.x;
    const int i = ij / KB_;
    float acc = 0.f;
    for (int s = threadIdx.x; s < SEQ_; s += 256) {
        float den = 0.f, num = 0.f;
#pragma unroll
        for (int tt = 0; tt < 4; tt++) {
            float2 p = g_dn[((size_t)tt * (B_ * KB_) + ij) * SEQ_ + s];
            den += p.x; num += p.y;
        }
        float sc = den > 0.f ? num / den : 0.f;
        acc += sc * (float)q_mask[i * SEQ_ + s];
    }
    red[threadIdx.x] = acc;
    __syncthreads();
    for (int st = 128; st > 0; st >>= 1) {
        if (threadIdx.x < st) red[threadIdx.x] += red[threadIdx.x + st];
        __syncthreads();
    }
    if (threadIdx.x == 0) out[ij] = red[0];
}

// ---------------------------------------------------------------------------
extern "C" void kernel_launch(void* const* d_in, const int* in_sizes, int n_in,
                              void* d_out, int out_size) {
    const float* q     = (const float*)d_in[0];
    const float* k     = (const float*)d_in[1];
    const float* alpha = (const float*)d_in[2];
    const int*   qm    = (const int*)d_in[3];
    const int*   km    = (const int*)d_in[4];
    float*       out   = (float*)d_out;

    cudaFuncSetAttribute(late_kernel, cudaFuncAttributeMaxDynamicSharedMemorySize, SMEM_DYN);

    normalize_kernel<<<((B_ + KB_) * SEQ_) / 8, 256>>>(q, k);

    dim3 grid(16, KB_, B_);   // (4 s-tiles x 4 t-tiles), j, i
    late_kernel<<<grid, 256, SMEM_DYN>>>(alpha, km);

    reduce_kernel<<<B_ * KB_, 256>>>(qm, out);
}

// round 5
// speedup vs baseline: 11.7933x; 2.1830x over previous
#include <cuda_runtime.h>
#include <cuda_fp16.h>
#include <math.h>
#include <stdint.h>

#define B_    8
#define KB_   16
#define SEQ_  512
#define HID_  768

#define BK 32
#define NKT (HID_ / BK)        // 24 k-iterations
#define ROWH 40                // padded halfs per smem row (80 bytes)
#define TILE_HALFS (128 * ROWH)
#define STAGE_BYTES (2 * TILE_HALFS * 2)   // A tile + B tile (20480 B)
#define SIDX_OFF (3 * STAGE_BYTES)         // 61440: 128 ints
#define TIDX_OFF (SIDX_OFF + 512)          // 128 ints
#define TAB_OFF  (TIDX_OFF + 512)          // 512 floats
#define SDN_OFF  (TAB_OFF + 2048)          // 2x128 float2
#define SMEM_DYN (SDN_OFF + 2048)          // 66560

// Compacted normalized fp16 operands (slot-major), index maps, counts
__device__ __half g_qh[B_ * SEQ_ * HID_];
__device__ __half g_kh[KB_ * SEQ_ * HID_];
__device__ int    g_pos[(B_ + KB_) * SEQ_];   // (b,s) -> compact slot or -1
__device__ int    g_idx[(B_ + KB_) * SEQ_];   // (b,slot) -> s or -1
__device__ int    g_cnt[B_ + KB_];
__device__ float2 g_dn[4 * B_ * KB_ * SEQ_];  // [t_tile][i][j][slot]

// ---------------- PTX helpers (baseline sm_80-level) ----------------
__device__ __forceinline__ uint32_t smem_u32(const void* p) {
    uint32_t a;
    asm("{ .reg .u64 t; cvta.to.shared.u64 t, %1; cvt.u32.u64 %0, t; }" : "=r"(a) : "l"(p));
    return a;
}
#define CP_ASYNC16(dst, src) \
    asm volatile("cp.async.cg.shared.global [%0], [%1], 16;" :: "r"(dst), "l"(src))
#define CP_COMMIT() asm volatile("cp.async.commit_group;" ::: "memory")
#define CP_WAIT(n)  asm volatile("cp.async.wait_group %0;" :: "n"(n) : "memory")

#define LDMATRIX_X4(r0, r1, r2, r3, addr) \
    asm volatile("ldmatrix.sync.aligned.m8n8.x4.shared.b16 {%0,%1,%2,%3}, [%4];" \
        : "=r"(r0), "=r"(r1), "=r"(r2), "=r"(r3) : "r"(addr))
#define LDMATRIX_X2(r0, r1, addr) \
    asm volatile("ldmatrix.sync.aligned.m8n8.x2.shared.b16 {%0,%1}, [%2];" \
        : "=r"(r0), "=r"(r1) : "r"(addr))

#define MMA16816(d, a, b) \
    asm volatile("mma.sync.aligned.m16n8k16.row.col.f32.f16.f16.f32 " \
        "{%0,%1,%2,%3}, {%4,%5,%6,%7}, {%8,%9}, {%0,%1,%2,%3};" \
        : "+f"((d)[0]), "+f"((d)[1]), "+f"((d)[2]), "+f"((d)[3]) \
        : "r"((a)[0]), "r"((a)[1]), "r"((a)[2]), "r"((a)[3]), "r"((b)[0]), "r"((b)[1]))

// ---------------------------------------------------------------------------
// Mask compaction: per batch-row b, rank valid positions. One block per b.
// ---------------------------------------------------------------------------
__global__ void scan_kernel(const int* __restrict__ qm, const int* __restrict__ km) {
    __shared__ int wsum[16], wbase[16], s_count;
    const int b = blockIdx.x;
    const int* m = (b < B_) ? (qm + b * SEQ_) : (km + (b - B_) * SEQ_);
    const int tid = threadIdx.x, wid = tid >> 5, lane = tid & 31;

    int valid = (m[tid] != 0);
    unsigned bal = __ballot_sync(0xffffffffu, valid);
    int lpre = __popc(bal & ((1u << lane) - 1u));
    if (lane == 31) wsum[wid] = lpre + valid;
    __syncthreads();
    if (wid == 0) {
        int v = (lane < 16) ? wsum[lane] : 0;
#pragma unroll
        for (int o = 1; o < 16; o <<= 1) {
            int t = __shfl_up_sync(0xffffffffu, v, o);
            if (lane >= o) v += t;
        }
        if (lane < 16) wbase[lane] = v - wsum[lane];
        if (lane == 15) s_count = v;
    }
    __syncthreads();
    int rank = wbase[wid] + lpre;
    g_pos[b * SEQ_ + tid] = valid ? rank : -1;
    if (valid) g_idx[b * SEQ_ + rank] = tid;
    if (tid >= s_count) g_idx[b * SEQ_ + tid] = -1;
    if (tid == 0) g_cnt[b] = s_count;
}

// ---------------------------------------------------------------------------
// L2-normalize valid rows -> fp16, written to compacted slot. Warp per row.
// ---------------------------------------------------------------------------
__global__ void normalize_kernel(const float* __restrict__ q,
                                 const float* __restrict__ k) {
    int warp_id = (blockIdx.x * blockDim.x + threadIdx.x) >> 5;
    int lane = threadIdx.x & 31;
    if (warp_id >= (B_ + KB_) * SEQ_) return;

    int pos = g_pos[warp_id];
    if (pos < 0) return;

    const int b = warp_id >> 9;        // batch-row index (q or k space)
    const float* src;
    __half* dst;
    if (b < B_) {
        src = q + (size_t)warp_id * HID_;
        dst = g_qh + ((size_t)b * SEQ_ + pos) * HID_;
    } else {
        src = k + ((size_t)(warp_id - B_ * SEQ_)) * HID_;
        dst = g_kh + ((size_t)(b - B_) * SEQ_ + pos) * HID_;
    }

    const float4* s4 = (const float4*)src;
    float4 v[6];
    float ss = 0.f;
#pragma unroll
    for (int g = 0; g < 6; g++) {
        v[g] = s4[lane + 32 * g];
        ss += v[g].x*v[g].x + v[g].y*v[g].y + v[g].z*v[g].z + v[g].w*v[g].w;
    }
#pragma unroll
    for (int o = 16; o > 0; o >>= 1) ss += __shfl_xor_sync(0xffffffffu, ss, o);
    float inv = 1.0f / fmaxf(sqrtf(ss), 1e-12f);

#pragma unroll
    for (int g = 0; g < 6; g++) {
        __half2 h0 = __floats2half2_rn(v[g].x * inv, v[g].y * inv);
        __half2 h1 = __floats2half2_rn(v[g].z * inv, v[g].w * inv);
        uint2 pk;
        pk.x = *(uint32_t*)&h0;
        pk.y = *(uint32_t*)&h1;
        *(uint2*)(dst + (lane + 32 * g) * 4) = pk;
    }
}

// ---------------------------------------------------------------------------
// HMMA GEMM on compacted operands + fused dw/softmax partial epilogue.
// CTA = (s_tile, t_tile, j, i); early-exit if tile beyond valid count.
// ---------------------------------------------------------------------------
__global__ __launch_bounds__(256, 1) void late_kernel(
    const float* __restrict__ alpha_raw) {

    const int st = blockIdx.x & 3, tt = blockIdx.x >> 2;
    const int j = blockIdx.y, i = blockIdx.z;

    const int cntS = g_cnt[i];
    const int cntT = g_cnt[B_ + j];
    if (st * 128 >= cntS || tt * 128 >= cntT) return;

    extern __shared__ __align__(16) char smem[];
    const uint32_t sb = smem_u32(smem);
    int*    sidx = (int*)(smem + SIDX_OFF);
    int*    tidx = (int*)(smem + TIDX_OFF);
    float*  tab  = (float*)(smem + TAB_OFF);
    float2* sdn  = (float2*)(smem + SDN_OFF);

    const int tid = threadIdx.x, wid = tid >> 5, lane = tid & 31;
    const int wm = wid & 3, wn = wid >> 2;

    const float ar = *alpha_raw;
    const float alpha = ar > 0.f ? ar : 0.01f * ar;
    if (tid < 128) {
        sidx[tid] = g_idx[i * SEQ_ + st * 128 + tid];
        tidx[tid] = g_idx[(B_ + j) * SEQ_ + tt * 128 + tid];
    }
    tab[tid]       = __expf(-alpha * (float)tid);
    tab[tid + 256] = __expf(-alpha * (float)(tid + 256));

    // cp.async source rows
    const int ldr = tid >> 1;
    const int ldc = (tid & 1) * 2;
    const __half* Arow = g_qh + ((size_t)(i * SEQ_ + st * 128 + ldr)) * HID_;
    const __half* Brow = g_kh + ((size_t)(j * SEQ_ + tt * 128 + ldr)) * HID_;
    const uint32_t dstA = sb + ldr * 80 + ldc * 16;
    const uint32_t dstB = dstA + TILE_HALFS * 2;

#pragma unroll
    for (int p = 0; p < 2; p++) {
        uint32_t o = p * STAGE_BYTES;
        const __half* a = Arow + p * BK + ldc * 8;
        const __half* b = Brow + p * BK + ldc * 8;
        CP_ASYNC16(dstA + o,      a);
        CP_ASYNC16(dstA + o + 16, a + 8);
        CP_ASYNC16(dstB + o,      b);
        CP_ASYNC16(dstB + o + 16, b + 8);
        CP_COMMIT();
    }

    float acc[2][8][4];
#pragma unroll
    for (int mi = 0; mi < 2; mi++)
#pragma unroll
        for (int ni = 0; ni < 8; ni++)
#pragma unroll
            for (int e = 0; e < 4; e++) acc[mi][ni][e] = 0.f;

    const uint32_t aAddrBase = sb + (wm * 32 + (lane & 15)) * 80 + ((lane >> 4) * 8) * 2;
    const uint32_t bAddrBase = sb + TILE_HALFS * 2 + (wn * 64 + (lane & 7)) * 80 + (((lane >> 3) & 1) * 8) * 2;

    for (int kt = 0; kt < NKT; kt++) {
        if (kt < NKT - 1) { CP_WAIT(1); } else { CP_WAIT(0); }
        __syncthreads();

        if (kt + 2 < NKT) {
            uint32_t o = ((kt + 2) % 3) * STAGE_BYTES;
            const __half* a = Arow + (kt + 2) * BK + ldc * 8;
            const __half* b = Brow + (kt + 2) * BK + ldc * 8;
            CP_ASYNC16(dstA + o,      a);
            CP_ASYNC16(dstA + o + 16, a + 8);
            CP_ASYNC16(dstB + o,      b);
            CP_ASYNC16(dstB + o + 16, b + 8);
            CP_COMMIT();
        }

        const uint32_t so = (kt % 3) * STAGE_BYTES;
#pragma unroll
        for (int k16 = 0; k16 < 2; k16++) {
            uint32_t af0[4], af1[4];
            LDMATRIX_X4(af0[0], af0[1], af0[2], af0[3], aAddrBase + so + k16 * 32);
            LDMATRIX_X4(af1[0], af1[1], af1[2], af1[3], aAddrBase + so + 16 * 80 + k16 * 32);
            uint32_t bf[8][2];
#pragma unroll
            for (int ni = 0; ni < 8; ni++)
                LDMATRIX_X2(bf[ni][0], bf[ni][1], bAddrBase + so + ni * 8 * 80 + k16 * 32);
#pragma unroll
            for (int ni = 0; ni < 8; ni++) {
                MMA16816(acc[0][ni], af0, bf[ni]);
                MMA16816(acc[1][ni], af1, bf[ni]);
            }
        }
    }
    __syncthreads();

    // ---- epilogue: table dw + exp + validity-select den/num partials ----
    float den[4] = {0.f, 0.f, 0.f, 0.f};
    float num[4] = {0.f, 0.f, 0.f, 0.f};
#pragma unroll
    for (int mi = 0; mi < 2; mi++) {
#pragma unroll
        for (int h = 0; h < 2; h++) {
            const int rloc = wm * 32 + mi * 16 + (lane >> 2) + h * 8;
            const int sraw = sidx[rloc];
            const int sv = sraw < 0 ? 0 : sraw;
#pragma unroll
            for (int ni = 0; ni < 8; ni++) {
#pragma unroll
                for (int e = 0; e < 2; e++) {
                    const int cloc = wn * 64 + ni * 8 + (lane & 3) * 2 + e;
                    const int traw = tidx[cloc];
                    const bool tv = traw >= 0;
                    const int t = tv ? traw : 0;
                    const float cosv = acc[mi][ni][h * 2 + e];
                    const float dw = tab[abs(sv - t)];
                    const float ev = tv ? __expf(cosv * dw) : 0.f;
                    const float cv = tv ? cosv : 0.f;
                    den[mi * 2 + h] += ev;
                    num[mi * 2 + h] = fmaf(ev, cv, num[mi * 2 + h]);
                }
            }
        }
    }
#pragma unroll
    for (int idx = 0; idx < 4; idx++) {
#pragma unroll
        for (int o = 1; o < 4; o <<= 1) {
            den[idx] += __shfl_xor_sync(0xffffffffu, den[idx], o);
            num[idx] += __shfl_xor_sync(0xffffffffu, num[idx], o);
        }
    }
    if ((lane & 3) == 0) {
#pragma unroll
        for (int mi = 0; mi < 2; mi++)
#pragma unroll
            for (int h = 0; h < 2; h++) {
                int rloc = wm * 32 + mi * 16 + (lane >> 2) + h * 8;
                sdn[wn * 128 + rloc] = make_float2(den[mi * 2 + h], num[mi * 2 + h]);
            }
    }
    __syncthreads();
    if (tid < 128) {
        float2 a = sdn[tid], b = sdn[128 + tid];
        g_dn[((size_t)tt * (B_ * KB_) + i * KB_ + j) * SEQ_ + st * 128 + tid] =
            make_float2(a.x + b.x, a.y + b.y);
    }
}

// ---------------------------------------------------------------------------
__global__ void reduce_kernel(float* __restrict__ out) {
    __shared__ float red[256];
    const int ij = blockIdx.x;
    const int i = ij / KB_, j = ij % KB_;
    const int ntt = (g_cnt[B_ + j] + 127) >> 7;
    const int nslot = g_cnt[i];
    float acc = 0.f;
    for (int s = threadIdx.x; s < nslot; s += 256) {
        float den = 0.f, num = 0.f;
        for (int tt = 0; tt < ntt; tt++) {
            float2 p = g_dn[((size_t)tt * (B_ * KB_) + ij) * SEQ_ + s];
            den += p.x; num += p.y;
        }
        if (den > 0.f) acc += num / den;
    }
    red[threadIdx.x] = acc;
    __syncthreads();
    for (int st = 128; st > 0; st >>= 1) {
        if (threadIdx.x < st) red[threadIdx.x] += red[threadIdx.x + st];
        __syncthreads();
    }
    if (threadIdx.x == 0) out[ij] = red[0];
}

// ---------------------------------------------------------------------------
extern "C" void kernel_launch(void* const* d_in, const int* in_sizes, int n_in,
                              void* d_out, int out_size) {
    const float* q     = (const float*)d_in[0];
    const float* k     = (const float*)d_in[1];
    const float* alpha = (const float*)d_in[2];
    const int*   qm    = (const int*)d_in[3];
    const int*   km    = (const int*)d_in[4];
    float*       out   = (float*)d_out;

    cudaFuncSetAttribute(late_kernel, cudaFuncAttributeMaxDynamicSharedMemorySize, SMEM_DYN);

    scan_kernel<<<B_ + KB_, 512>>>(qm, km);
    normalize_kernel<<<((B_ + KB_) * SEQ_) / 8, 256>>>(q, k);

    dim3 grid(16, KB_, B_);
    late_kernel<<<grid, 256, SMEM_DYN>>>(alpha);

    reduce_kernel<<<B_ * KB_, 256>>>(out);
}

// round 6
// speedup vs baseline: 14.1065x; 1.1961x over previous
#include <cuda_runtime.h>
#include <cuda_fp16.h>
#include <math.h>
#include <stdint.h>

#define B_    8
#define KB_   16
#define SEQ_  512
#define HID_  768

#define BK 32
#define NKT (HID_ / BK)        // 24 k-iterations
#define ROWH 40                // padded halfs per smem row (80 bytes)
#define TILE_HALFS (128 * ROWH)
#define STAGE_BYTES (2 * TILE_HALFS * 2)   // A tile + B tile (20480 B)
#define SIDX_OFF (3 * STAGE_BYTES)         // 61440: 128 ints
#define TIDX_OFF (SIDX_OFF + 512)          // 128 ints
#define TAB_OFF  (TIDX_OFF + 512)          // 512 floats
#define SDN_OFF  (TAB_OFF + 2048)          // 2x128 float2
#define SMEM_DYN (SDN_OFF + 2048)          // 66560

// Compacted normalized fp16 operands (slot-major), index maps, counts
__device__ __half g_qh[B_ * SEQ_ * HID_];
__device__ __half g_kh[KB_ * SEQ_ * HID_];
__device__ int    g_pos[(B_ + KB_) * SEQ_];   // (b,s) -> compact slot or -1
__device__ int    g_idx[(B_ + KB_) * SEQ_];   // (b,slot) -> s or -1
__device__ int    g_cnt[B_ + KB_];
__device__ float2 g_dn[4 * B_ * KB_ * SEQ_];  // [t_tile][i][j][slot]

// ---------------- PTX helpers (baseline sm_80-level) ----------------
__device__ __forceinline__ uint32_t smem_u32(const void* p) {
    uint32_t a;
    asm("{ .reg .u64 t; cvta.to.shared.u64 t, %1; cvt.u32.u64 %0, t; }" : "=r"(a) : "l"(p));
    return a;
}
#define CP_ASYNC16(dst, src) \
    asm volatile("cp.async.cg.shared.global [%0], [%1], 16;" :: "r"(dst), "l"(src))
#define CP_COMMIT() asm volatile("cp.async.commit_group;" ::: "memory")
#define CP_WAIT(n)  asm volatile("cp.async.wait_group %0;" :: "n"(n) : "memory")

#define LDMATRIX_X4(r0, r1, r2, r3, addr) \
    asm volatile("ldmatrix.sync.aligned.m8n8.x4.shared.b16 {%0,%1,%2,%3}, [%4];" \
        : "=r"(r0), "=r"(r1), "=r"(r2), "=r"(r3) : "r"(addr))
#define LDMATRIX_X2(r0, r1, addr) \
    asm volatile("ldmatrix.sync.aligned.m8n8.x2.shared.b16 {%0,%1}, [%2];" \
        : "=r"(r0), "=r"(r1) : "r"(addr))

#define MMA16816(d, a, b) \
    asm volatile("mma.sync.aligned.m16n8k16.row.col.f32.f16.f16.f32 " \
        "{%0,%1,%2,%3}, {%4,%5,%6,%7}, {%8,%9}, {%0,%1,%2,%3};" \
        : "+f"((d)[0]), "+f"((d)[1]), "+f"((d)[2]), "+f"((d)[3]) \
        : "r"((a)[0]), "r"((a)[1]), "r"((a)[2]), "r"((a)[3]), "r"((b)[0]), "r"((b)[1]))

// ---------------------------------------------------------------------------
// Mask compaction: per batch-row b, rank valid positions. One block per b.
// ---------------------------------------------------------------------------
__global__ void scan_kernel(const int* __restrict__ qm, const int* __restrict__ km) {
    __shared__ int wsum[16], wbase[16], s_count;
    const int b = blockIdx.x;
    const int* m = (b < B_) ? (qm + b * SEQ_) : (km + (b - B_) * SEQ_);
    const int tid = threadIdx.x, wid = tid >> 5, lane = tid & 31;

    int valid = (m[tid] != 0);
    unsigned bal = __ballot_sync(0xffffffffu, valid);
    int lpre = __popc(bal & ((1u << lane) - 1u));
    if (lane == 31) wsum[wid] = lpre + valid;
    __syncthreads();
    if (wid == 0) {
        int v = (lane < 16) ? wsum[lane] : 0;
#pragma unroll
        for (int o = 1; o < 16; o <<= 1) {
            int t = __shfl_up_sync(0xffffffffu, v, o);
            if (lane >= o) v += t;
        }
        if (lane < 16) wbase[lane] = v - wsum[lane];
        if (lane == 15) s_count = v;
    }
    __syncthreads();
    int rank = wbase[wid] + lpre;
    g_pos[b * SEQ_ + tid] = valid ? rank : -1;
    if (valid) g_idx[b * SEQ_ + rank] = tid;
    if (tid >= s_count) g_idx[b * SEQ_ + tid] = -1;
    if (tid == 0) g_cnt[b] = s_count;
}

// ---------------------------------------------------------------------------
// L2-normalize valid rows -> fp16, written to compacted slot. Warp per row.
// ---------------------------------------------------------------------------
__global__ void normalize_kernel(const float* __restrict__ q,
                                 const float* __restrict__ k) {
    int warp_id = (blockIdx.x * blockDim.x + threadIdx.x) >> 5;
    int lane = threadIdx.x & 31;
    if (warp_id >= (B_ + KB_) * SEQ_) return;

    int pos = g_pos[warp_id];
    if (pos < 0) return;

    const int b = warp_id >> 9;
    const float* src;
    __half* dst;
    if (b < B_) {
        src = q + (size_t)warp_id * HID_;
        dst = g_qh + ((size_t)b * SEQ_ + pos) * HID_;
    } else {
        src = k + ((size_t)(warp_id - B_ * SEQ_)) * HID_;
        dst = g_kh + ((size_t)(b - B_) * SEQ_ + pos) * HID_;
    }

    const float4* s4 = (const float4*)src;
    float4 v[6];
    float ss = 0.f;
#pragma unroll
    for (int g = 0; g < 6; g++) {
        v[g] = s4[lane + 32 * g];
        ss += v[g].x*v[g].x + v[g].y*v[g].y + v[g].z*v[g].z + v[g].w*v[g].w;
    }
#pragma unroll
    for (int o = 16; o > 0; o >>= 1) ss += __shfl_xor_sync(0xffffffffu, ss, o);
    float inv = 1.0f / fmaxf(sqrtf(ss), 1e-12f);

#pragma unroll
    for (int g = 0; g < 6; g++) {
        __half2 h0 = __floats2half2_rn(v[g].x * inv, v[g].y * inv);
        __half2 h1 = __floats2half2_rn(v[g].z * inv, v[g].w * inv);
        uint2 pk;
        pk.x = *(uint32_t*)&h0;
        pk.y = *(uint32_t*)&h1;
        *(uint2*)(dst + (lane + 32 * g) * 4) = pk;
    }
}

// ---------------------------------------------------------------------------
// HMMA GEMM on compacted operands + fused dw/softmax partial epilogue.
// CTA = (s_tile, t_tile, j, i); early-exit if tile beyond valid count.
// 2 CTAs/SM for latency hiding (4 warps/SMSP).
// ---------------------------------------------------------------------------
__global__ __launch_bounds__(256, 2) void late_kernel(
    const float* __restrict__ alpha_raw) {

    const int st = blockIdx.x & 3, tt = blockIdx.x >> 2;
    const int j = blockIdx.y, i = blockIdx.z;

    const int cntS = g_cnt[i];
    const int cntT = g_cnt[B_ + j];
    if (st * 128 >= cntS || tt * 128 >= cntT) return;

    extern __shared__ __align__(16) char smem[];
    const uint32_t sb = smem_u32(smem);
    int*    sidx = (int*)(smem + SIDX_OFF);
    int*    tidx = (int*)(smem + TIDX_OFF);
    float*  tab  = (float*)(smem + TAB_OFF);
    float2* sdn  = (float2*)(smem + SDN_OFF);

    const int tid = threadIdx.x, wid = tid >> 5, lane = tid & 31;
    const int wm = wid & 3, wn = wid >> 2;

    const float ar = *alpha_raw;
    const float alpha = ar > 0.f ? ar : 0.01f * ar;
    if (tid < 128) {
        sidx[tid] = g_idx[i * SEQ_ + st * 128 + tid];
        tidx[tid] = g_idx[(B_ + j) * SEQ_ + tt * 128 + tid];
    }
    tab[tid]       = __expf(-alpha * (float)tid);
    tab[tid + 256] = __expf(-alpha * (float)(tid + 256));

    // cp.async source rows
    const int ldr = tid >> 1;
    const int ldc = (tid & 1) * 2;
    const __half* Arow = g_qh + ((size_t)(i * SEQ_ + st * 128 + ldr)) * HID_;
    const __half* Brow = g_kh + ((size_t)(j * SEQ_ + tt * 128 + ldr)) * HID_;
    const uint32_t dstA = sb + ldr * 80 + ldc * 16;
    const uint32_t dstB = dstA + TILE_HALFS * 2;

#pragma unroll
    for (int p = 0; p < 2; p++) {
        uint32_t o = p * STAGE_BYTES;
        const __half* a = Arow + p * BK + ldc * 8;
        const __half* b = Brow + p * BK + ldc * 8;
        CP_ASYNC16(dstA + o,      a);
        CP_ASYNC16(dstA + o + 16, a + 8);
        CP_ASYNC16(dstB + o,      b);
        CP_ASYNC16(dstB + o + 16, b + 8);
        CP_COMMIT();
    }

    float acc[2][8][4];
#pragma unroll
    for (int mi = 0; mi < 2; mi++)
#pragma unroll
        for (int ni = 0; ni < 8; ni++)
#pragma unroll
            for (int e = 0; e < 4; e++) acc[mi][ni][e] = 0.f;

    const uint32_t aAddrBase = sb + (wm * 32 + (lane & 15)) * 80 + ((lane >> 4) * 8) * 2;
    const uint32_t bAddrBase = sb + TILE_HALFS * 2 + (wn * 64 + (lane & 7)) * 80 + (((lane >> 3) & 1) * 8) * 2;

    for (int kt = 0; kt < NKT; kt++) {
        if (kt < NKT - 1) { CP_WAIT(1); } else { CP_WAIT(0); }
        __syncthreads();

        if (kt + 2 < NKT) {
            uint32_t o = ((kt + 2) % 3) * STAGE_BYTES;
            const __half* a = Arow + (kt + 2) * BK + ldc * 8;
            const __half* b = Brow + (kt + 2) * BK + ldc * 8;
            CP_ASYNC16(dstA + o,      a);
            CP_ASYNC16(dstA + o + 16, a + 8);
            CP_ASYNC16(dstB + o,      b);
            CP_ASYNC16(dstB + o + 16, b + 8);
            CP_COMMIT();
        }

        const uint32_t so = (kt % 3) * STAGE_BYTES;
#pragma unroll
        for (int k16 = 0; k16 < 2; k16++) {
            uint32_t af0[4], af1[4];
            LDMATRIX_X4(af0[0], af0[1], af0[2], af0[3], aAddrBase + so + k16 * 32);
            LDMATRIX_X4(af1[0], af1[1], af1[2], af1[3], aAddrBase + so + 16 * 80 + k16 * 32);
            uint32_t bf[8][2];
#pragma unroll
            for (int ni = 0; ni < 8; ni++)
                LDMATRIX_X2(bf[ni][0], bf[ni][1], bAddrBase + so + ni * 8 * 80 + k16 * 32);
#pragma unroll
            for (int ni = 0; ni < 8; ni++) {
                MMA16816(acc[0][ni], af0, bf[ni]);
                MMA16816(acc[1][ni], af1, bf[ni]);
            }
        }
    }
    __syncthreads();

    // ---- epilogue: table dw + exp + validity-select den/num partials ----
    float den[4] = {0.f, 0.f, 0.f, 0.f};
    float num[4] = {0.f, 0.f, 0.f, 0.f};
#pragma unroll
    for (int mi = 0; mi < 2; mi++) {
#pragma unroll
        for (int h = 0; h < 2; h++) {
            const int rloc = wm * 32 + mi * 16 + (lane >> 2) + h * 8;
            const int sraw = sidx[rloc];
            const int sv = sraw < 0 ? 0 : sraw;
#pragma unroll
            for (int ni = 0; ni < 8; ni++) {
#pragma unroll
                for (int e = 0; e < 2; e++) {
                    const int cloc = wn * 64 + ni * 8 + (lane & 3) * 2 + e;
                    const int traw = tidx[cloc];
                    const bool tv = traw >= 0;
                    const int t = tv ? traw : 0;
                    const float cosv = acc[mi][ni][h * 2 + e];
                    const float dw = tab[abs(sv - t)];
                    const float ev = tv ? __expf(cosv * dw) : 0.f;
                    const float cv = tv ? cosv : 0.f;
                    den[mi * 2 + h] += ev;
                    num[mi * 2 + h] = fmaf(ev, cv, num[mi * 2 + h]);
                }
            }
        }
    }
#pragma unroll
    for (int idx = 0; idx < 4; idx++) {
#pragma unroll
        for (int o = 1; o < 4; o <<= 1) {
            den[idx] += __shfl_xor_sync(0xffffffffu, den[idx], o);
            num[idx] += __shfl_xor_sync(0xffffffffu, num[idx], o);
        }
    }
    if ((lane & 3) == 0) {
#pragma unroll
        for (int mi = 0; mi < 2; mi++)
#pragma unroll
            for (int h = 0; h < 2; h++) {
                int rloc = wm * 32 + mi * 16 + (lane >> 2) + h * 8;
                sdn[wn * 128 + rloc] = make_float2(den[mi * 2 + h], num[mi * 2 + h]);
            }
    }
    __syncthreads();
    if (tid < 128) {
        float2 a = sdn[tid], b = sdn[128 + tid];
        g_dn[((size_t)tt * (B_ * KB_) + i * KB_ + j) * SEQ_ + st * 128 + tid] =
            make_float2(a.x + b.x, a.y + b.y);
    }
}

// ---------------------------------------------------------------------------
// Warp per (i,j) pair: 128 pairs = 16 blocks x 8 warps.
// ---------------------------------------------------------------------------
__global__ void reduce_kernel(float* __restrict__ out) {
    const int ij = blockIdx.x * 8 + (threadIdx.x >> 5);
    const int lane = threadIdx.x & 31;
    const int i = ij / KB_, j = ij % KB_;
    const int ntt = (g_cnt[B_ + j] + 127) >> 7;
    const int nslot = g_cnt[i];
    float acc = 0.f;
    for (int s = lane; s < nslot; s += 32) {
        float den = 0.f, num = 0.f;
        for (int tt = 0; tt < ntt; tt++) {
            float2 p = g_dn[((size_t)tt * (B_ * KB_) + ij) * SEQ_ + s];
            den += p.x; num += p.y;
        }
        if (den > 0.f) acc += num / den;
    }
#pragma unroll
    for (int o = 16; o > 0; o >>= 1) acc += __shfl_xor_sync(0xffffffffu, acc, o);
    if (lane == 0) out[ij] = acc;
}

// ---------------------------------------------------------------------------
extern "C" void kernel_launch(void* const* d_in, const int* in_sizes, int n_in,
                              void* d_out, int out_size) {
    const float* q     = (const float*)d_in[0];
    const float* k     = (const float*)d_in[1];
    const float* alpha = (const float*)d_in[2];
    const int*   qm    = (const int*)d_in[3];
    const int*   km    = (const int*)d_in[4];
    float*       out   = (float*)d_out;

    cudaFuncSetAttribute(late_kernel, cudaFuncAttributeMaxDynamicSharedMemorySize, SMEM_DYN);

    scan_kernel<<<B_ + KB_, 512>>>(qm, km);
    normalize_kernel<<<((B_ + KB_) * SEQ_) / 8, 256>>>(q, k);

    dim3 grid(16, KB_, B_);
    late_kernel<<<grid, 256, SMEM_DYN>>>(alpha);

    reduce_kernel<<<16, 256>>>(out);
}